// round 1
// baseline (speedup 1.0000x reference)
#include <cuda_runtime.h>

// y = x*2 + 5 - 3/(1+x), elementwise over 8192*8192 fp32.
// Memory-bound: 512 MB traffic -> ~64 us floor at 8 TB/s.

__global__ void elementwise_f4_kernel(const float4* __restrict__ in,
                                      float4* __restrict__ out,
                                      int n4) {
    int i = blockIdx.x * blockDim.x + threadIdx.x;
    if (i < n4) {
        float4 v = __ldg(&in[i]);
        float4 r;
        r.x = fmaf(v.x, 2.0f, 5.0f) - 3.0f / (1.0f + v.x);
        r.y = fmaf(v.y, 2.0f, 5.0f) - 3.0f / (1.0f + v.y);
        r.z = fmaf(v.z, 2.0f, 5.0f) - 3.0f / (1.0f + v.z);
        r.w = fmaf(v.w, 2.0f, 5.0f) - 3.0f / (1.0f + v.w);
        out[i] = r;
    }
}

extern "C" void kernel_launch(void* const* d_in, const int* in_sizes, int n_in,
                              void* d_out, int out_size) {
    const float* x = (const float*)d_in[0];
    float* y = (float*)d_out;
    int n = in_sizes[0];          // 67108864, divisible by 4
    int n4 = n >> 2;              // 16777216 float4 elements

    const int threads = 256;
    int blocks = (n4 + threads - 1) / threads;
    elementwise_f4_kernel<<<blocks, threads>>>(
        (const float4*)x, (float4*)y, n4);
}

// round 2
// speedup vs baseline: 1.0463x; 1.0463x over previous
#include <cuda_runtime.h>

// y = x*2 + 5 - 3/(1+x), elementwise over 8192*8192 fp32 (64M elems).
// HBM-bound streaming kernel. R2: 4x float4 per thread (front-batched MLP=4)
// + streaming cache hints (ld.global.cs / st.global.cs) to cut L2 residency.

constexpr int V = 4;  // float4 per thread

__global__ void elementwise_f4x4_kernel(const float4* __restrict__ in,
                                        float4* __restrict__ out,
                                        int n4) {
    // Block-contiguous, warp-coalesced: block covers blockDim*V consecutive
    // float4s; thread t handles t, t+blockDim, t+2*blockDim, t+3*blockDim.
    int base = blockIdx.x * (blockDim.x * V) + threadIdx.x;

    float4 v[V];
#pragma unroll
    for (int k = 0; k < V; k++) {
        v[k] = __ldcs(&in[base + k * blockDim.x]);   // front-batched loads
    }

#pragma unroll
    for (int k = 0; k < V; k++) {
        float4 r;
        r.x = fmaf(v[k].x, 2.0f, 5.0f) - 3.0f / (1.0f + v[k].x);
        r.y = fmaf(v[k].y, 2.0f, 5.0f) - 3.0f / (1.0f + v[k].y);
        r.z = fmaf(v[k].z, 2.0f, 5.0f) - 3.0f / (1.0f + v[k].z);
        r.w = fmaf(v[k].w, 2.0f, 5.0f) - 3.0f / (1.0f + v[k].w);
        __stcs(&out[base + k * blockDim.x], r);
    }
}

extern "C" void kernel_launch(void* const* d_in, const int* in_sizes, int n_in,
                              void* d_out, int out_size) {
    const float* x = (const float*)d_in[0];
    float* y = (float*)d_out;
    int n = in_sizes[0];          // 67108864 = 8192*8192
    int n4 = n >> 2;              // 16777216 float4

    const int threads = 256;
    // Exact division: 16777216 / (256*4) = 16384 blocks, no tail.
    int blocks = n4 / (threads * V);
    elementwise_f4x4_kernel<<<blocks, threads>>>(
        (const float4*)x, (float4*)y, n4);
}

// round 3
// speedup vs baseline: 1.0488x; 1.0023x over previous
#include <cuda_runtime.h>

// y = x*2 + 5 - 3/(1+x), elementwise over 8192*8192 fp32 (64M elems).
// R3: 8x float4 per thread (front-batched MLP=8) + streaming cache hints.

constexpr int V = 8;  // float4 per thread

__global__ __launch_bounds__(256)
void elementwise_f4x8_kernel(const float4* __restrict__ in,
                             float4* __restrict__ out) {
    // Block covers blockDim*V consecutive float4s; thread t handles
    // t + k*blockDim for k in [0,V) — fully coalesced per iteration.
    int base = blockIdx.x * (256 * V) + threadIdx.x;

    float4 v[V];
#pragma unroll
    for (int k = 0; k < V; k++) {
        v[k] = __ldcs(&in[base + k * 256]);   // 8 independent LDG.128, front-batched
    }

#pragma unroll
    for (int k = 0; k < V; k++) {
        float4 r;
        r.x = fmaf(v[k].x, 2.0f, 5.0f) - 3.0f / (1.0f + v[k].x);
        r.y = fmaf(v[k].y, 2.0f, 5.0f) - 3.0f / (1.0f + v[k].y);
        r.z = fmaf(v[k].z, 2.0f, 5.0f) - 3.0f / (1.0f + v[k].z);
        r.w = fmaf(v[k].w, 2.0f, 5.0f) - 3.0f / (1.0f + v[k].w);
        __stcs(&out[base + k * 256], r);
    }
}

extern "C" void kernel_launch(void* const* d_in, const int* in_sizes, int n_in,
                              void* d_out, int out_size) {
    const float* x = (const float*)d_in[0];
    float* y = (float*)d_out;
    int n = in_sizes[0];          // 67108864 = 8192*8192
    int n4 = n >> 2;              // 16777216 float4

    const int threads = 256;
    // Exact division: 16777216 / (256*8) = 8192 blocks, no tail.
    int blocks = n4 / (threads * V);
    elementwise_f4x8_kernel<<<blocks, threads>>>(
        (const float4*)x, (float4*)y);
}